// round 3
// baseline (speedup 1.0000x reference)
#include <cuda_runtime.h>

// ---------------------------------------------------------------------------
// AttentionLayer: context = softmax(Q K^T) V, scores = sum_q probs
//   Q = query @ Wq + bq   [pairs,256,1024]
//   K = source @ Wk + bk  [pairs,512,1024]
//   V = source @ Wv + bv  [pairs,512,1024]
// pairs = 8*32 = 256. All GEMMs done in 3xTF32 (fp32-accurate) on mma.sync.
// ---------------------------------------------------------------------------

#define HID   1024
#define SEQQ  256
#define SEQK  512
#define PAIRS 256
#define MQ    (PAIRS * SEQQ)   // 65536
#define MS    (PAIRS * SEQK)   // 131072

// Scratch (allocation-free rule: __device__ globals)
__device__ float g_Q[(size_t)MQ * HID];
__device__ float g_K[(size_t)MS * HID];
__device__ float g_V[(size_t)MS * HID];
__device__ float g_S[(size_t)PAIRS * SEQQ * SEQK];

// ---------------------------------------------------------------------------
// helpers
// ---------------------------------------------------------------------------
__device__ __forceinline__ void split_tf32(float x, unsigned &hi, unsigned &lo) {
    unsigned h;
    asm("cvt.rna.tf32.f32 %0, %1;" : "=r"(h) : "f"(x));
    hi = h;
    lo = __float_as_uint(x - __uint_as_float(h));
}

__device__ __forceinline__ void mma_tf32(float c[4], const unsigned a[4], const unsigned b[2]) {
    asm("mma.sync.aligned.m16n8k8.row.col.f32.tf32.tf32.f32 "
        "{%0,%1,%2,%3}, {%4,%5,%6,%7}, {%8,%9}, {%0,%1,%2,%3};"
        : "+f"(c[0]), "+f"(c[1]), "+f"(c[2]), "+f"(c[3])
        : "r"(a[0]), "r"(a[1]), "r"(a[2]), "r"(a[3]), "r"(b[0]), "r"(b[1]));
}

// ---------------------------------------------------------------------------
// Generic 3xTF32 GEMM: C[M,N] = A[M,K] * B + bias
//   TRANSB = false: B is [K,N] row-major (ldb = row stride)
//   TRANSB = true : B is [N,K] row-major (C = A * B^T)
// Block tile 128x128x16, 256 threads (8 warps, 2x4), warp tile 64x32.
// M,N implied by grid (must be multiples of 128); K multiple of 16.
// blockIdx.z = batch index with given strides.
// ---------------------------------------------------------------------------
template <bool TRANSB, bool BIAS>
__global__ void __launch_bounds__(256, 1)
gemm3x(const float* __restrict__ A, const float* __restrict__ B,
       const float* __restrict__ bias, float* __restrict__ C,
       int K, int lda, int ldb, int ldc,
       size_t sA, size_t sB, size_t sC)
{
    __shared__ float As[128 * 20];   // As[row*20 + k], padded stride -> conflict-free frags
    __shared__ float Bs[16 * 136];   // Bs[k*136 + n]

    const int tid  = threadIdx.x;
    const int lane = tid & 31;
    const int wm   = (tid >> 5) >> 2;   // 0..1
    const int wn   = (tid >> 5) & 3;    // 0..3
    const int g    = lane >> 2;         // 0..7
    const int tg   = lane & 3;          // 0..3

    const size_t z = blockIdx.z;
    A += z * sA + (size_t)blockIdx.y * 128 * lda;
    if (TRANSB) B += z * sB + (size_t)blockIdx.x * 128 * ldb;
    else        B += z * sB + (size_t)blockIdx.x * 128;
    C += z * sC + (size_t)blockIdx.y * 128 * ldc + (size_t)blockIdx.x * 128;

    // per-thread global->smem coordinates (2 float4 each for A and B)
    const int p0 = tid, p1 = tid + 256;
    const int aR0 = p0 >> 2, aK0 = (p0 & 3) * 4;
    const int aR1 = p1 >> 2, aK1 = (p1 & 3) * 4;
    int bY0, bX0, bY1, bX1;
    if (TRANSB) { bY0 = p0 >> 2; bX0 = (p0 & 3) * 4;  bY1 = p1 >> 2; bX1 = (p1 & 3) * 4; }  // bY=n, bX=k
    else        { bY0 = p0 >> 5; bX0 = (p0 & 31) * 4; bY1 = p1 >> 5; bX1 = (p1 & 31) * 4; } // bY=k, bX=n

    float4 ra0, ra1, rb0, rb1;

    auto load_tile = [&](int t) {
        const float* At = A + (size_t)t * 16;
        ra0 = *(const float4*)(At + (size_t)aR0 * lda + aK0);
        ra1 = *(const float4*)(At + (size_t)aR1 * lda + aK1);
        if (TRANSB) {
            const float* Bt = B + (size_t)t * 16;
            rb0 = *(const float4*)(Bt + (size_t)bY0 * ldb + bX0);
            rb1 = *(const float4*)(Bt + (size_t)bY1 * ldb + bX1);
        } else {
            const float* Bt = B + (size_t)t * 16 * ldb;
            rb0 = *(const float4*)(Bt + (size_t)bY0 * ldb + bX0);
            rb1 = *(const float4*)(Bt + (size_t)bY1 * ldb + bX1);
        }
    };
    auto stage = [&]() {
        *(float4*)&As[aR0 * 20 + aK0] = ra0;
        *(float4*)&As[aR1 * 20 + aK1] = ra1;
        if (TRANSB) {
            Bs[(bX0 + 0) * 136 + bY0] = rb0.x; Bs[(bX0 + 1) * 136 + bY0] = rb0.y;
            Bs[(bX0 + 2) * 136 + bY0] = rb0.z; Bs[(bX0 + 3) * 136 + bY0] = rb0.w;
            Bs[(bX1 + 0) * 136 + bY1] = rb1.x; Bs[(bX1 + 1) * 136 + bY1] = rb1.y;
            Bs[(bX1 + 2) * 136 + bY1] = rb1.z; Bs[(bX1 + 3) * 136 + bY1] = rb1.w;
        } else {
            *(float4*)&Bs[bY0 * 136 + bX0] = rb0;
            *(float4*)&Bs[bY1 * 136 + bX1] = rb1;
        }
    };

    float acc[4][4][4];
    #pragma unroll
    for (int mi = 0; mi < 4; ++mi)
        #pragma unroll
        for (int ni = 0; ni < 4; ++ni)
            #pragma unroll
            for (int i = 0; i < 4; ++i) acc[mi][ni][i] = 0.f;

    const int nT = K >> 4;
    load_tile(0);
    stage();
    __syncthreads();

    for (int t = 0; t < nT; ++t) {
        if (t + 1 < nT) load_tile(t + 1);   // LDGs in flight during compute

        #pragma unroll
        for (int kk = 0; kk < 2; ++kk) {
            unsigned ahi[4][4], alo[4][4];
            #pragma unroll
            for (int mi = 0; mi < 4; ++mi) {
                const int r = wm * 64 + mi * 16 + g;
                const int k = kk * 8 + tg;
                float a0 = As[r * 20 + k];
                float a1 = As[(r + 8) * 20 + k];
                float a2 = As[r * 20 + k + 4];
                float a3 = As[(r + 8) * 20 + k + 4];
                split_tf32(a0, ahi[mi][0], alo[mi][0]);
                split_tf32(a1, ahi[mi][1], alo[mi][1]);
                split_tf32(a2, ahi[mi][2], alo[mi][2]);
                split_tf32(a3, ahi[mi][3], alo[mi][3]);
            }
            unsigned bhi[4][2], blo[4][2];
            #pragma unroll
            for (int ni = 0; ni < 4; ++ni) {
                const int cn = wn * 32 + ni * 8 + g;
                const int k = kk * 8 + tg;
                float b0 = Bs[k * 136 + cn];
                float b1 = Bs[(k + 4) * 136 + cn];
                split_tf32(b0, bhi[ni][0], blo[ni][0]);
                split_tf32(b1, bhi[ni][1], blo[ni][1]);
            }
            #pragma unroll
            for (int mi = 0; mi < 4; ++mi)
                #pragma unroll
                for (int ni = 0; ni < 4; ++ni) {
                    mma_tf32(acc[mi][ni], ahi[mi], bhi[ni]);
                    mma_tf32(acc[mi][ni], alo[mi], bhi[ni]);
                    mma_tf32(acc[mi][ni], ahi[mi], blo[ni]);
                }
        }
        __syncthreads();
        if (t + 1 < nT) { stage(); __syncthreads(); }
    }

    // epilogue
    const float* bptr = BIAS ? (bias + (size_t)blockIdx.x * 128) : bias;
    #pragma unroll
    for (int mi = 0; mi < 4; ++mi) {
        const int r = wm * 64 + mi * 16 + g;
        #pragma unroll
        for (int ni = 0; ni < 4; ++ni) {
            const int cn = wn * 32 + ni * 8 + tg * 2;
            float b0 = 0.f, b1 = 0.f;
            if (BIAS) { b0 = bptr[cn]; b1 = bptr[cn + 1]; }
            float2 v0 = make_float2(acc[mi][ni][0] + b0, acc[mi][ni][1] + b1);
            float2 v1 = make_float2(acc[mi][ni][2] + b0, acc[mi][ni][3] + b1);
            *(float2*)(C + (size_t)r * ldc + cn)       = v0;
            *(float2*)(C + (size_t)(r + 8) * ldc + cn) = v1;
        }
    }
}

// ---------------------------------------------------------------------------
// Softmax over rows of S [pairs,256,512] in place + column-sum into scores.
// grid (32 row-blocks, 256 pairs), 256 threads = 8 warps, warp per row.
// ---------------------------------------------------------------------------
__global__ void __launch_bounds__(256)
softmax_scores(float* __restrict__ S, float* __restrict__ scores)
{
    const int pair = blockIdx.y;
    const int w    = threadIdx.x >> 5;
    const int lane = threadIdx.x & 31;

    __shared__ float colsum[SEQK];
    for (int i = threadIdx.x; i < SEQK; i += 256) colsum[i] = 0.f;
    __syncthreads();

    float* row = S + (size_t)pair * SEQQ * SEQK + (size_t)(blockIdx.x * 8 + w) * SEQK;

    float v[16];
    #pragma unroll
    for (int i = 0; i < 16; ++i) v[i] = row[lane + 32 * i];

    float m = v[0];
    #pragma unroll
    for (int i = 1; i < 16; ++i) m = fmaxf(m, v[i]);
    #pragma unroll
    for (int o = 16; o; o >>= 1) m = fmaxf(m, __shfl_xor_sync(0xffffffffu, m, o));

    float s = 0.f;
    #pragma unroll
    for (int i = 0; i < 16; ++i) { v[i] = __expf(v[i] - m); s += v[i]; }
    #pragma unroll
    for (int o = 16; o; o >>= 1) s += __shfl_xor_sync(0xffffffffu, s, o);

    const float inv = 1.f / s;
    #pragma unroll
    for (int i = 0; i < 16; ++i) {
        const float p = v[i] * inv;
        row[lane + 32 * i] = p;
        atomicAdd(&colsum[lane + 32 * i], p);
    }
    __syncthreads();
    for (int i = threadIdx.x; i < SEQK; i += 256)
        atomicAdd(&scores[(size_t)pair * SEQK + i], colsum[i]);
}

// ---------------------------------------------------------------------------
// kernel_launch
// inputs (metadata order): query, source, Wq, bq, Wk, bk, Wv, bv
// output: context [8,32,256,1024] then attention_scores [8,32,512]
// ---------------------------------------------------------------------------
extern "C" void kernel_launch(void* const* d_in, const int* in_sizes, int n_in,
                              void* d_out, int out_size)
{
    const float* query  = (const float*)d_in[0];
    const float* source = (const float*)d_in[1];
    const float* Wq = (const float*)d_in[2];
    const float* bq = (const float*)d_in[3];
    const float* Wk = (const float*)d_in[4];
    const float* bk = (const float*)d_in[5];
    const float* Wv = (const float*)d_in[6];
    const float* bv = (const float*)d_in[7];

    float* ctx    = (float*)d_out;
    float* scores = ctx + (size_t)PAIRS * SEQQ * HID;

    float *Q, *Kb, *Vb, *S;
    cudaGetSymbolAddress((void**)&Q,  g_Q);
    cudaGetSymbolAddress((void**)&Kb, g_K);
    cudaGetSymbolAddress((void**)&Vb, g_V);
    cudaGetSymbolAddress((void**)&S,  g_S);

    cudaMemsetAsync(scores, 0, (size_t)PAIRS * SEQK * sizeof(float));

    dim3 blk(256);
    // projections (M = 65536 / 131072, N = K = 1024)
    gemm3x<false, true><<<dim3(HID / 128, MQ / 128, 1), blk>>>(
        query, Wq, bq, Q, HID, HID, HID, HID, 0, 0, 0);
    gemm3x<false, true><<<dim3(HID / 128, MS / 128, 1), blk>>>(
        source, Wk, bk, Kb, HID, HID, HID, HID, 0, 0, 0);
    gemm3x<false, true><<<dim3(HID / 128, MS / 128, 1), blk>>>(
        source, Wv, bv, Vb, HID, HID, HID, HID, 0, 0, 0);
    // logits S = Q K^T (batched over pairs)
    gemm3x<true, false><<<dim3(SEQK / 128, SEQQ / 128, PAIRS), blk>>>(
        Q, Kb, nullptr, S, HID, HID, HID, SEQK,
        (size_t)SEQQ * HID, (size_t)SEQK * HID, (size_t)SEQQ * SEQK);
    // softmax + scores
    softmax_scores<<<dim3(SEQQ / 8, PAIRS), 256>>>(S, scores);
    // context = P V (batched)
    gemm3x<false, false><<<dim3(HID / 128, SEQQ / 128, PAIRS), blk>>>(
        S, Vb, nullptr, ctx, SEQK, SEQK, HID, HID,
        (size_t)SEQQ * SEQK, (size_t)SEQK * HID, (size_t)SEQQ * HID);
}